// round 12
// baseline (speedup 1.0000x reference)
#include <cuda_runtime.h>

// SSKernelDiag: out[h,l] = 2 * Re( sum_n Cc[h,n] * A[h,n]^l )
//   A = exp(abslog + i*phase), dtA = abslog + i*phase, Cc = C*(A-1)/dtA
// H=256, N=64, L=4096, CH=1.
//
// R12: two-kernel pipeline (K1 dedups the O(N^2) sort + Cc transcendentals)
// + 4-way head split in K2 to shatter the heavy slow-decay heads that
// dominated R11's elapsed. K2: grid 1024 = (head, part<4); block owns tiles
// tl = part + 4j (j in [0,32)), warp owns j = warp + 8k (k in [0,4)).
// Rank-sorted n (desc l_cut) -> each tile's active set is a rank prefix.
// Inner: 2 LDS.128 (W bcast) + 4 LDS.64 (q) + 4 FFMA2 per 4 active ranks.

#define HH 256
#define NN 64
#define LL 4096
#define TILE 32
#define NTILES 128
#define PARTS 4
#define JT 32              // tiles per block
#define NTHREADS 256
#define NWARPS 8
#define KPW 4              // tiles per warp in K2
#define CUT 23.0f          // e^-23 ~ 1e-10 magnitude cutoff

typedef unsigned long long ull;

__device__ float4 g_prep[HH * NN];      // rank-indexed (al, ph, Ccx, Ccy)
__device__ int    g_cnt[HH * NTILES];   // active ranks per tile, ceil to 4

__device__ __forceinline__ float2 cmul(float2 a, float2 b) {
    return make_float2(fmaf(a.x, b.x, -(a.y * b.y)),
                       fmaf(a.x, b.y,  (a.y * b.x)));
}
// exp(i*y), 2-term Cody-Waite reduction; accurate for |y| <~ 2^14.
__device__ __forceinline__ float2 cis_cw(float y) {
    float m = rintf(y * 0.15915494309189535f);
    float r = fmaf(m, -6.28125f, y);
    r = fmaf(m, -1.9353072e-3f, r);
    float s, c;
    __sincosf(r, &s, &c);
    return make_float2(c, s);
}
__device__ __forceinline__ float2 apow(float al, float ph, float f) {
    float2 cs = cis_cw(ph * f);
    float  e  = __expf(al * f);
    return make_float2(e * cs.x, e * cs.y);
}
__device__ __forceinline__ ull pack2(float x, float y) {
    ull r;
    asm("mov.b64 %0, {%1, %2};" : "=l"(r) : "f"(x), "f"(y));
    return r;
}
__device__ __forceinline__ float2 unpack2(ull v) {
    float x, y;
    asm("mov.b64 {%0, %1}, %2;" : "=f"(x), "=f"(y) : "l"(v));
    return make_float2(x, y);
}
__device__ __forceinline__ void ffma2(ull& acc, ull a, ull b) {
    asm("fma.rn.f32x2 %0, %1, %2, %0;" : "+l"(acc) : "l"(a), "l"(b));
}

// ---------------- Kernel 1: per-head prep ----------------
__global__ void __launch_bounds__(NN)
ssk_prep_kernel(const float* __restrict__ abslog,
                const float* __restrict__ phase,
                const float* __restrict__ C) {
    __shared__ int lcut[NN];

    const int h = blockIdx.x;
    const int n = threadIdx.x;

    const float al = abslog[h * NN + n];
    const float ph = phase[h * NN + n];
    lcut[n] = (int)fminf((float)LL, CUT / (-al) + 1.0f);
    __syncthreads();

    // rank (desc l_cut, index tiebreak)
    const int my = lcut[n];
    int rank = 0;
    #pragma unroll 8
    for (int m = 0; m < NN; m++) {
        const int o = lcut[m];
        rank += (o > my) || (o == my && m < n);
    }

    // Cc = 2 * C * (A - 1) / dtA
    float er = __expf(al);
    float s0, c0;
    __sincosf(ph, &s0, &c0);
    float2 Am1 = make_float2(er * c0 - 1.0f, er * s0);
    float2 Cin = reinterpret_cast<const float2*>(C)[h * NN + n];
    float2 num = cmul(Cin, Am1);
    float  inv = 1.0f / fmaf(al, al, ph * ph);
    float  ccx = 2.0f * (num.x * al + num.y * ph) * inv;
    float  ccy = 2.0f * (num.y * al - num.x * ph) * inv;
    g_prep[h * NN + rank] = make_float4(al, ph, ccx, ccy);

    // per-tile counts: thread n handles tiles n and n+64
    #pragma unroll
    for (int d = 0; d < 2; d++) {
        const int tl = n + d * NN;
        const int lmin = TILE * tl;
        int c = 0;
        #pragma unroll 8
        for (int m = 0; m < NN; m++) c += (lcut[m] > lmin);
        g_cnt[h * NTILES + tl] = (c + 3) & ~3;
    }
}

// ---------------- Kernel 2: main evaluation ----------------
__global__ void __launch_bounds__(NTHREADS)
ssk_main_kernel(float* __restrict__ out) {
    __shared__ float  alR[NN], phR[NN];
    __shared__ float2 CcR[NN];
    __shared__ int    scnt[JT];
    __shared__ float2 sQr[NN][TILE];        // 16 KB: conj-packed A^t, rank idx
    __shared__ float2 sWbuf[NWARPS][NN];    // 4 KB: per-warp W staging

    const int bid  = blockIdx.x;
    const int h    = bid >> 2;
    const int part = bid & (PARTS - 1);
    const int tid  = threadIdx.x;
    const int warp = tid >> 5;
    const int lane = tid & 31;

    // load prepped params (rank-indexed) + owned-tile counts
    if (tid < NN) {
        float4 p = g_prep[h * NN + tid];
        alR[tid] = p.x;
        phR[tid] = p.y;
        CcR[tid] = make_float2(p.z, p.w);
    } else if (tid < NN + JT) {
        const int j = tid - NN;
        scnt[j] = g_cnt[h * NTILES + part + PARTS * j];
    }
    __syncthreads();

    // sQr[r][t] = conj-packed A^t ; thread = (r, quarter of 8 t's)
    {
        const int r  = tid & 63;
        const int q8 = tid >> 6;             // [0,4)
        const float al = alR[r];
        const float ph = phR[r];
        float2 P  = apow(al, ph, 8.0f * (float)q8);
        float2 A1 = apow(al, ph, 1.0f);
        #pragma unroll
        for (int j = 0; j < 8; j++) {
            sQr[r][8 * q8 + j] = make_float2(P.x, -P.y);
            P = cmul(P, A1);
        }
    }

    // per-lane W state (ranks lane, lane+32); first tile part+4*warp,
    // tile stride per k is 32 tiles -> step A^1024
    float2 W0, W1, S0, S1;
    {
        const float a0 = alR[lane],      p0 = phR[lane];
        const float a1 = alR[lane + 32], p1 = phR[lane + 32];
        const float e0 = (float)(TILE * (part + PARTS * warp));
        W0 = cmul(CcR[lane],      apow(a0, p0, e0));
        W1 = cmul(CcR[lane + 32], apow(a1, p1, e0));
        S0 = apow(a0, p0, 1024.0f);
        S1 = apow(a1, p1, 1024.0f);
    }
    __syncthreads();

    // main: 4 tiles per warp; j = warp + 8k, tl = part + 4j
    float* outh = out + h * LL;
    const ulonglong2* wb = reinterpret_cast<const ulonglong2*>(sWbuf[warp]);

    #pragma unroll
    for (int k = 0; k < KPW; k++) {
        const int j  = warp + NWARPS * k;
        const int tl = part + PARTS * j;
        __syncwarp();
        sWbuf[warp][lane]      = W0;
        sWbuf[warp][lane + 32] = W1;
        __syncwarp();

        const int m = scnt[j];
        ull acc = pack2(0.0f, 0.0f);
        for (int r = 0; r < m; r += 4) {
            ulonglong2 wa = wb[(r >> 1)];
            ulonglong2 wc = wb[(r >> 1) + 1];
            ull q0 = *reinterpret_cast<const ull*>(&sQr[r + 0][lane]);
            ull q1 = *reinterpret_cast<const ull*>(&sQr[r + 1][lane]);
            ull q2 = *reinterpret_cast<const ull*>(&sQr[r + 2][lane]);
            ull q3 = *reinterpret_cast<const ull*>(&sQr[r + 3][lane]);
            ffma2(acc, wa.x, q0);
            ffma2(acc, wa.y, q1);
            ffma2(acc, wc.x, q2);
            ffma2(acc, wc.y, q3);
        }
        float2 u = unpack2(acc);
        outh[TILE * tl + lane] = u.x + u.y;

        W0 = cmul(W0, S0);
        W1 = cmul(W1, S1);
    }
}

extern "C" void kernel_launch(void* const* d_in, const int* in_sizes, int n_in,
                              void* d_out, int out_size) {
    const float* abslog = (const float*)d_in[0];  // (H, N) f32
    const float* phase  = (const float*)d_in[1];  // (H, N) f32
    const float* C      = (const float*)d_in[2];  // (1, H, N, 2) f32
    float* out = (float*)d_out;                   // (1, H, L) f32

    ssk_prep_kernel<<<HH, NN>>>(abslog, phase, C);
    ssk_main_kernel<<<HH * PARTS, NTHREADS>>>(out);
}

// round 13
// speedup vs baseline: 1.2851x; 1.2851x over previous
#include <cuda_runtime.h>

// SSKernelDiag: out[h,l] = 2 * Re( sum_n Cc[h,n] * A[h,n]^l )
//   A = exp(abslog + i*phase), dtA = abslog + i*phase, Cc = C*(A-1)/dtA
// H=256, N=64, L=4096, CH=1.
//
// R13: single fused kernel (no K1 launch overhead), PARTS=2. Decay
// truncation with rank-sorted n (desc l_cut) -> per-tile active rank prefix.
// Lean prologue: phase1 lcut; phase2 rank+Cc (from regs) + per-tile counts
// (threads 64..127); phase3 sQr + W init. Main: 8 tiles/warp, inner
// 2 LDS.128 (W) + 4 LDS.64 (q) + 4 FFMA2 (dual acc) per 4 active ranks.

#define HH 256
#define NN 64
#define LL 4096
#define TILE 32
#define PARTS 2
#define JT 64              // tiles per block
#define NTHREADS 256
#define NWARPS 8
#define KPW 8              // tiles per warp
#define CUT 23.0f          // e^-23 ~ 1e-10 magnitude cutoff

typedef unsigned long long ull;

__device__ __forceinline__ float2 cmul(float2 a, float2 b) {
    return make_float2(fmaf(a.x, b.x, -(a.y * b.y)),
                       fmaf(a.x, b.y,  (a.y * b.x)));
}
// exp(i*y), 2-term Cody-Waite reduction; accurate for |y| <~ 2^14.
__device__ __forceinline__ float2 cis_cw(float y) {
    float m = rintf(y * 0.15915494309189535f);
    float r = fmaf(m, -6.28125f, y);
    r = fmaf(m, -1.9353072e-3f, r);
    float s, c;
    __sincosf(r, &s, &c);
    return make_float2(c, s);
}
__device__ __forceinline__ float2 apow(float al, float ph, float f) {
    float2 cs = cis_cw(ph * f);
    float  e  = __expf(al * f);
    return make_float2(e * cs.x, e * cs.y);
}
__device__ __forceinline__ ull pack2(float x, float y) {
    ull r;
    asm("mov.b64 %0, {%1, %2};" : "=l"(r) : "f"(x), "f"(y));
    return r;
}
__device__ __forceinline__ float2 unpack2(ull v) {
    float x, y;
    asm("mov.b64 {%0, %1}, %2;" : "=f"(x), "=f"(y) : "l"(v));
    return make_float2(x, y);
}
__device__ __forceinline__ void ffma2(ull& acc, ull a, ull b) {
    asm("fma.rn.f32x2 %0, %1, %2, %0;" : "+l"(acc) : "l"(a), "l"(b));
}
__device__ __forceinline__ ull fadd2(ull a, ull b) {
    ull r;
    asm("add.rn.f32x2 %0, %1, %2;" : "=l"(r) : "l"(a), "l"(b));
    return r;
}

__global__ void __launch_bounds__(NTHREADS)
ssk_diag_kernel(const float* __restrict__ abslog,
                const float* __restrict__ phase,
                const float* __restrict__ C,
                float* __restrict__ out) {
    __shared__ float  alR[NN], phR[NN];
    __shared__ float2 CcR[NN];
    __shared__ int    lcut[NN];
    __shared__ int    scnt[JT];
    __shared__ float2 sQr[NN][TILE];        // 16 KB: conj-packed A^t, rank idx
    __shared__ float2 sWbuf[NWARPS][NN];    // 4 KB: per-warp W staging

    const int bid  = blockIdx.x;
    const int h    = bid >> 1;
    const int part = bid & 1;
    const int tid  = threadIdx.x;
    const int warp = tid >> 5;
    const int lane = tid & 31;

    // ---- phase 1: params + lcut (threads 0..63) ----
    float al = 0.f, ph = 0.f;
    float2 Cin = make_float2(0.f, 0.f);
    if (tid < NN) {
        al  = abslog[h * NN + tid];
        ph  = phase[h * NN + tid];
        Cin = reinterpret_cast<const float2*>(C)[h * NN + tid];
        lcut[tid] = (int)fminf((float)LL, CUT / (-al) + 1.0f);
    }
    __syncthreads();

    // ---- phase 2: rank + Cc scatter (0..63); tile counts (64..127) ----
    if (tid < NN) {
        const int my = lcut[tid];
        int rank = 0;
        #pragma unroll 8
        for (int m = 0; m < NN; m++) {
            const int o = lcut[m];
            rank += (o > my) || (o == my && m < tid);
        }
        float er = __expf(al);
        float s0, c0;
        __sincosf(ph, &s0, &c0);
        float2 Am1 = make_float2(er * c0 - 1.0f, er * s0);
        float2 num = cmul(Cin, Am1);
        float  inv = 1.0f / fmaf(al, al, ph * ph);
        alR[rank] = al;
        phR[rank] = ph;
        CcR[rank] = make_float2(2.0f * (num.x * al + num.y * ph) * inv,
                                2.0f * (num.y * al - num.x * ph) * inv);
    } else if (tid < NN + JT) {
        const int j = tid - NN;
        const int lmin = TILE * (part + PARTS * j);
        int c = 0;
        #pragma unroll 8
        for (int m = 0; m < NN; m++) c += (lcut[m] > lmin);
        scnt[j] = (c + 3) & ~3;
    }
    __syncthreads();

    // ---- phase 3a: sQr[r][t] = conj-packed A^t; thread = (r, q8) ----
    {
        const int r  = tid & 63;
        const int q8 = tid >> 6;             // [0,4)
        const float a = alR[r];
        const float p = phR[r];
        float2 P  = apow(a, p, 8.0f * (float)q8);
        float2 A1 = apow(a, p, 1.0f);
        #pragma unroll
        for (int j = 0; j < 8; j++) {
            sQr[r][8 * q8 + j] = make_float2(P.x, -P.y);
            P = cmul(P, A1);
        }
    }
    // ---- phase 3b: per-lane W state (ranks lane, lane+32); step A^512 ----
    float2 W0, W1, S0, S1;
    {
        const float a0 = alR[lane],      p0 = phR[lane];
        const float a1 = alR[lane + 32], p1 = phR[lane + 32];
        const float e0 = (float)(TILE * (part + PARTS * warp));
        W0 = cmul(CcR[lane],      apow(a0, p0, e0));
        W1 = cmul(CcR[lane + 32], apow(a1, p1, e0));
        S0 = apow(a0, p0, 512.0f);           // tile stride 16 -> 32*16
        S1 = apow(a1, p1, 512.0f);
    }
    __syncthreads();

    // ---- main: 8 tiles per warp; j = warp + 8k, tl = part + 2j ----
    float* outh = out + h * LL;
    const ulonglong2* wb = reinterpret_cast<const ulonglong2*>(sWbuf[warp]);

    #pragma unroll
    for (int k = 0; k < KPW; k++) {
        const int j  = warp + NWARPS * k;
        const int tl = part + PARTS * j;
        __syncwarp();
        sWbuf[warp][lane]      = W0;
        sWbuf[warp][lane + 32] = W1;
        __syncwarp();

        const int m = scnt[j];
        ull acc0 = pack2(0.0f, 0.0f);
        ull acc1 = acc0;
        for (int r = 0; r < m; r += 4) {
            ulonglong2 wa = wb[(r >> 1)];
            ulonglong2 wc = wb[(r >> 1) + 1];
            ull q0 = *reinterpret_cast<const ull*>(&sQr[r + 0][lane]);
            ull q1 = *reinterpret_cast<const ull*>(&sQr[r + 1][lane]);
            ull q2 = *reinterpret_cast<const ull*>(&sQr[r + 2][lane]);
            ull q3 = *reinterpret_cast<const ull*>(&sQr[r + 3][lane]);
            ffma2(acc0, wa.x, q0);
            ffma2(acc1, wa.y, q1);
            ffma2(acc0, wc.x, q2);
            ffma2(acc1, wc.y, q3);
        }
        float2 u = unpack2(fadd2(acc0, acc1));
        outh[TILE * tl + lane] = u.x + u.y;

        W0 = cmul(W0, S0);
        W1 = cmul(W1, S1);
    }
}

extern "C" void kernel_launch(void* const* d_in, const int* in_sizes, int n_in,
                              void* d_out, int out_size) {
    const float* abslog = (const float*)d_in[0];  // (H, N) f32
    const float* phase  = (const float*)d_in[1];  // (H, N) f32
    const float* C      = (const float*)d_in[2];  // (1, H, N, 2) f32
    float* out = (float*)d_out;                   // (1, H, L) f32

    ssk_diag_kernel<<<HH * PARTS, NTHREADS>>>(abslog, phase, C, out);
}